// round 10
// baseline (speedup 1.0000x reference)
#include <cuda_runtime.h>
#include <cstdint>

// ---------------- problem constants ----------------
#define HD      512
#define ROPE_D  64
#define RATIO   4
#define B_      4
#define S_      4096
#define H_      4096
#define C_      1024            // S_/RATIO
#define MDIM    (B_ * S_)       // 16384
#define NDIM    (4 * HD)        // 2048 = kv(1024) ++ gate(1024)
#define KDIM    H_              // 4096

// ---------------- GEMM tiling ----------------
#define BM      128
#define BN      128
#define BK      32
#define STAGES  3
#define PITCH   36              // floats per smem row (32 data + 4 pad, conflict-free)

// 128 MB scratch: raw logits, row-major [MDIM][NDIM], cols 0..1023 = kv, 1024..2047 = gate
__device__ float g_scratch[(size_t)MDIM * NDIM];

// ---------------- helpers ----------------
__device__ __forceinline__ uint32_t f2tf(float x) {
    uint32_t u;
    asm("cvt.rna.tf32.f32 %0, %1;" : "=r"(u) : "f"(x));
    return u;
}

__device__ __forceinline__ void mma8(float* c, const uint32_t* a, uint32_t b0, uint32_t b1) {
    asm volatile(
        "mma.sync.aligned.m16n8k8.row.col.f32.tf32.tf32.f32 "
        "{%0,%1,%2,%3}, {%4,%5,%6,%7}, {%8,%9}, {%0,%1,%2,%3};"
        : "+f"(c[0]), "+f"(c[1]), "+f"(c[2]), "+f"(c[3])
        : "r"(a[0]), "r"(a[1]), "r"(a[2]), "r"(a[3]), "r"(b0), "r"(b1));
}

__device__ __forceinline__ void cp16(void* dst, const void* src) {
    unsigned d = (unsigned)__cvta_generic_to_shared(dst);
    asm volatile("cp.async.cg.shared.global [%0], [%1], 16;" :: "r"(d), "l"(src));
}

// ============================================================
// Pass 1: TF32 GEMM  scratch[m][n] = x[m,:] . W[n,:]
//   n < 1024 -> W_kv row n ;  n >= 1024 -> W_gate row n-1024
// ============================================================
__global__ void __launch_bounds__(256)
gemm_tf32_kernel(const float* __restrict__ X,
                 const float* __restrict__ Wkv,
                 const float* __restrict__ Wg) {
    extern __shared__ float sm[];
    float* As = sm;                         // STAGES * BM * PITCH
    float* Bs = sm + STAGES * BM * PITCH;   // STAGES * BN * PITCH

    const int bid   = blockIdx.x;
    const int ntile = bid & 15;     // N-fast rasterization: wave keeps W hot in L2
    const int mtile = bid >> 4;
    const int m0 = mtile * BM;
    const int n0 = ntile * BN;
    const float* Wsrc = (ntile < 8) ? (Wkv + (size_t)n0 * KDIM)
                                    : (Wg  + (size_t)(n0 - 1024) * KDIM);

    const int tid  = threadIdx.x;
    const int lane = tid & 31;
    const int warp = tid >> 5;
    const int wm   = warp >> 1;     // 0..3  (M direction, 32 rows each)
    const int wn   = warp & 1;      // 0..1  (N direction, 64 cols each)

    // gmem->smem mapping: 16B per thread, 32 rows per pass, 4 passes (128 rows)
    const int lrow = tid >> 3;          // 0..31
    const int lcol = (tid & 7) << 2;    // 0,4,...,28

    const float* aG = X    + (size_t)(m0 + lrow) * KDIM + lcol;
    const float* bG = Wsrc + (size_t)lrow        * KDIM + lcol;

    // ---------- prologue: stages 0..STAGES-2 ----------
#pragma unroll
    for (int s = 0; s < STAGES - 1; s++) {
        float* aD = As + s * BM * PITCH + lrow * PITCH + lcol;
        float* bD = Bs + s * BM * PITCH + lrow * PITCH + lcol;
#pragma unroll
        for (int p = 0; p < 4; p++) {
            cp16(aD + p * 32 * PITCH, aG + (size_t)p * 32 * KDIM + s * BK);
            cp16(bD + p * 32 * PITCH, bG + (size_t)p * 32 * KDIM + s * BK);
        }
        asm volatile("cp.async.commit_group;");
    }

    float acc[2][8][4];
#pragma unroll
    for (int i = 0; i < 2; i++)
#pragma unroll
        for (int j = 0; j < 8; j++)
#pragma unroll
            for (int k = 0; k < 4; k++) acc[i][j][k] = 0.f;

    const int KT = KDIM / BK;   // 128
    for (int it = 0; it < KT; it++) {
        asm volatile("cp.async.wait_group 1;");
        __syncthreads();

        const int nk = it + STAGES - 1;
        if (nk < KT) {
            const int st = nk % STAGES;
            float* aD = As + st * BM * PITCH + lrow * PITCH + lcol;
            float* bD = Bs + st * BM * PITCH + lrow * PITCH + lcol;
#pragma unroll
            for (int p = 0; p < 4; p++) {
                cp16(aD + p * 32 * PITCH, aG + (size_t)p * 32 * KDIM + nk * BK);
                cp16(bD + p * 32 * PITCH, bG + (size_t)p * 32 * KDIM + nk * BK);
            }
        }
        asm volatile("cp.async.commit_group;");

        const float* Asm = As + (it % STAGES) * BM * PITCH;
        const float* Bsm = Bs + (it % STAGES) * BM * PITCH;

#pragma unroll
        for (int kk = 0; kk < 4; kk++) {
            const int k0 = kk * 8 + (lane & 3);
            uint32_t af[2][4];
#pragma unroll
            for (int mi = 0; mi < 2; mi++) {
                const int rb = wm * 32 + mi * 16 + (lane >> 2);
                af[mi][0] = f2tf(Asm[rb * PITCH + k0]);
                af[mi][1] = f2tf(Asm[(rb + 8) * PITCH + k0]);
                af[mi][2] = f2tf(Asm[rb * PITCH + k0 + 4]);
                af[mi][3] = f2tf(Asm[(rb + 8) * PITCH + k0 + 4]);
            }
#pragma unroll
            for (int ni = 0; ni < 8; ni++) {
                const int cb = wn * 64 + ni * 8 + (lane >> 2);
                const uint32_t b0 = f2tf(Bsm[cb * PITCH + k0]);
                const uint32_t b1 = f2tf(Bsm[cb * PITCH + k0 + 4]);
                mma8(acc[0][ni], af[0], b0, b1);
                mma8(acc[1][ni], af[1], b0, b1);
            }
        }
    }

    // ---------- epilogue: write raw logits ----------
#pragma unroll
    for (int mi = 0; mi < 2; mi++) {
        const int row = m0 + wm * 32 + mi * 16 + (lane >> 2);
#pragma unroll
        for (int ni = 0; ni < 8; ni++) {
            const int col = n0 + wn * 64 + ni * 8 + (lane & 3) * 2;
            float2 v0 = make_float2(acc[mi][ni][0], acc[mi][ni][1]);
            float2 v1 = make_float2(acc[mi][ni][2], acc[mi][ni][3]);
            *reinterpret_cast<float2*>(&g_scratch[(size_t)row * NDIM + col])       = v0;
            *reinterpret_cast<float2*>(&g_scratch[(size_t)(row + 8) * NDIM + col]) = v1;
        }
    }
}

// ============================================================
// Pass 2: gate * sigmoid, softmax-weighted chunk combine,
//         RMS-norm, RoPE on last 64 dims. One block per (b,c).
// ============================================================
__device__ __forceinline__ float sigmoidf_(float x) {
    return 1.0f / (1.0f + expf(-x));
}

__global__ void __launch_bounds__(512)
combine_kernel(const float* __restrict__ cosb,
               const float* __restrict__ sinb,
               const float* __restrict__ ape,
               const float* __restrict__ normw,
               float* __restrict__ out) {
    const int bc = blockIdx.x;
    const int b = bc >> 10;         // / C_
    const int c = bc & (C_ - 1);
    const int d = threadIdx.x;      // 0..511

    // ape_comb[8][512]: rows 0..3 = ape[r, d], rows 4..7 = ape[r, 512+d]
    float v[8];
#pragma unroll
    for (int r = 0; r < 4; r++) {
        v[r]     = ape[r * 1024 + d];
        v[4 + r] = ape[r * 1024 + 512 + d];
    }

    const size_t mb = (size_t)(b * S_ + c * RATIO);
    float acc = 0.f;

    if (c == 0) {
        // w0 = softmax(ape[:, :HD]) over 4 rows; main only
        float mx = fmaxf(fmaxf(v[0], v[1]), fmaxf(v[2], v[3]));
        float e[4], s = 0.f;
#pragma unroll
        for (int r = 0; r < 4; r++) { e[r] = expf(v[r] - mx); s += e[r]; }
        const float inv = 1.0f / s;
#pragma unroll
        for (int r = 0; r < 4; r++) {
            const size_t row = mb + r;
            const float kvv = g_scratch[row * NDIM + d];
            const float gv  = g_scratch[row * NDIM + 1024 + d];
            acc += kvv * sigmoidf_(gv) * (e[r] * inv);
        }
    } else {
        // w8 = softmax over 8 rows; main uses w8[0:4], ov(prev chunk) uses w8[4:8]
        float mx = v[0];
#pragma unroll
        for (int r = 1; r < 8; r++) mx = fmaxf(mx, v[r]);
        float e[8], s = 0.f;
#pragma unroll
        for (int r = 0; r < 8; r++) { e[r] = expf(v[r] - mx); s += e[r]; }
        const float inv = 1.0f / s;
#pragma unroll
        for (int r = 0; r < 4; r++) {
            const size_t row = mb + r;
            const float kvv = g_scratch[row * NDIM + d];
            const float gv  = g_scratch[row * NDIM + 1024 + d];
            acc += kvv * sigmoidf_(gv) * (e[r] * inv);
        }
#pragma unroll
        for (int r = 0; r < 4; r++) {
            const size_t row = mb - RATIO + r;
            const float ovv = g_scratch[row * NDIM + 512 + d];
            const float gv  = g_scratch[row * NDIM + 1536 + d];
            acc += ovv * sigmoidf_(gv) * (e[4 + r] * inv);
        }
    }

    // ---- RMS norm over d (512) ----
    __shared__ float red[16];
    __shared__ float sv[512];
    __shared__ float s_scale;

    float sq = acc * acc;
#pragma unroll
    for (int o = 16; o > 0; o >>= 1) sq += __shfl_xor_sync(0xffffffffu, sq, o);
    const int wid = d >> 5, ln = d & 31;
    if (ln == 0) red[wid] = sq;
    __syncthreads();
    if (d == 0) {
        float t = 0.f;
#pragma unroll
        for (int i = 0; i < 16; i++) t += red[i];
        s_scale = rsqrtf(t * (1.0f / 512.0f) + 1e-6f);
    }
    __syncthreads();

    const float y = acc * s_scale * normw[d];
    sv[d] = y;
    __syncthreads();

    // ---- RoPE on dims [448, 512) ----
    float res;
    if (d < HD - ROPE_D) {
        res = y;
    } else {
        const int j = d - (HD - ROPE_D);
        const int i = j >> 1;
        const float e = sv[(HD - ROPE_D) + 2 * i];
        const float o = sv[(HD - ROPE_D) + 2 * i + 1];
        const size_t ci = (size_t)(b * C_ + c) * (ROPE_D / 2) + i;
        const float cs = cosb[ci];
        const float sn = sinb[ci];
        res = ((j & 1) == 0) ? (e * cs - o * sn) : (e * sn + o * cs);
    }
    out[(size_t)(b * C_ + c) * HD + d] = res;
}

// ============================================================
// launch
// ============================================================
extern "C" void kernel_launch(void* const* d_in, const int* in_sizes, int n_in,
                              void* d_out, int out_size) {
    const float* x    = (const float*)d_in[0];
    const float* cosb = (const float*)d_in[1];
    const float* sinb = (const float*)d_in[2];
    const float* Wkv  = (const float*)d_in[3];
    const float* Wg   = (const float*)d_in[4];
    const float* ape  = (const float*)d_in[5];
    const float* nw   = (const float*)d_in[6];
    float* out = (float*)d_out;

    const size_t smem = (size_t)STAGES * (BM + BN) * PITCH * sizeof(float); // 110592
    cudaFuncSetAttribute(gemm_tf32_kernel,
                         cudaFuncAttributeMaxDynamicSharedMemorySize, (int)smem);

    gemm_tf32_kernel<<<(MDIM / BM) * (NDIM / BN), 256, smem>>>(x, Wkv, Wg);
    combine_kernel<<<B_ * C_, 512>>>(cosb, sinb, ape, nw, out);
}

// round 12
// speedup vs baseline: 1.0831x; 1.0831x over previous
#include <cuda_runtime.h>
#include <cstdint>

// ---------------- problem constants ----------------
#define HD      512
#define ROPE_D  64
#define RATIO   4
#define B_      4
#define S_      4096
#define H_      4096
#define C_      1024            // S_/RATIO
#define MDIM    (B_ * S_)       // 16384
#define NDIM    (4 * HD)        // 2048 = kv(1024) ++ gate(1024)
#define KDIM    H_              // 4096

// ---------------- GEMM tiling ----------------
#define BM      128
#define BN      256
#define BK      32
#define STAGES  4
#define PITCH   36              // floats per smem row (32 data + 4 pad, conflict-free)
#define KT      (KDIM / BK)     // 128

// 128 MB scratch: raw logits [MDIM][NDIM]; cols 0..1023 = kv, 1024..2047 = gate
__device__ float g_scratch[(size_t)MDIM * NDIM];

// ---------------- helpers ----------------
__device__ __forceinline__ uint32_t f2tf(float x) {
    uint32_t u;
    asm("cvt.rna.tf32.f32 %0, %1;" : "=r"(u) : "f"(x));
    return u;
}

__device__ __forceinline__ void mma8(float* c, const uint32_t* a, uint32_t b0, uint32_t b1) {
    asm volatile(
        "mma.sync.aligned.m16n8k8.row.col.f32.tf32.tf32.f32 "
        "{%0,%1,%2,%3}, {%4,%5,%6,%7}, {%8,%9}, {%0,%1,%2,%3};"
        : "+f"(c[0]), "+f"(c[1]), "+f"(c[2]), "+f"(c[3])
        : "r"(a[0]), "r"(a[1]), "r"(a[2]), "r"(a[3]), "r"(b0), "r"(b1));
}

__device__ __forceinline__ void cp16(void* dst, const void* src) {
    unsigned d = (unsigned)__cvta_generic_to_shared(dst);
    asm volatile("cp.async.cg.shared.global [%0], [%1], 16;" :: "r"(d), "l"(src));
}

// ============================================================
// Pass 1: TF32 GEMM  scratch[m][n] = x[m,:] . W[n,:]
//   CTA 128x256, 8 warps (2M x 4N), warp tile 64x64, 4-stage cp.async
// ============================================================
__global__ void __launch_bounds__(256, 1)
gemm_tf32_kernel(const float* __restrict__ X,
                 const float* __restrict__ Wkv,
                 const float* __restrict__ Wg) {
    extern __shared__ float sm[];
    float* As = sm;                          // STAGES * BM * PITCH floats
    float* Bs = sm + STAGES * BM * PITCH;    // STAGES * BN * PITCH floats

    const int bid   = blockIdx.x;
    const int ntile = bid & 7;      // N-fast raster keeps W hot in L2
    const int mtile = bid >> 3;
    const int m0 = mtile * BM;
    const int n0 = ntile * BN;
    const float* Wsrc = (ntile < 4) ? (Wkv + (size_t)n0 * KDIM)
                                    : (Wg  + (size_t)(n0 - 1024) * KDIM);

    const int tid  = threadIdx.x;
    const int lane = tid & 31;
    const int warp = tid >> 5;
    const int wm   = warp >> 2;     // 0..1  (64 rows each)
    const int wn   = warp & 3;      // 0..3  (64 cols each)

    // gmem->smem: 16B per thread, 32 rows per pass
    const int lrow = tid >> 3;          // 0..31
    const int lcol = (tid & 7) << 2;    // 0..28

    const float* aG = X    + (size_t)(m0 + lrow) * KDIM + lcol;
    const float* bG = Wsrc + (size_t)lrow        * KDIM + lcol;

    auto load_stage = [&](int st, int kt) {
        float* aD = As + st * BM * PITCH + lrow * PITCH + lcol;
        float* bD = Bs + st * BN * PITCH + lrow * PITCH + lcol;
        const int kof = kt * BK;
#pragma unroll
        for (int p = 0; p < 4; p++)       // A: 128 rows
            cp16(aD + p * 32 * PITCH, aG + (size_t)p * 32 * KDIM + kof);
#pragma unroll
        for (int p = 0; p < 8; p++)       // B: 256 rows
            cp16(bD + p * 32 * PITCH, bG + (size_t)p * 32 * KDIM + kof);
    };

    // ---------- prologue: stages 0..2 ----------
#pragma unroll
    for (int s = 0; s < STAGES - 1; s++) {
        load_stage(s, s);
        asm volatile("cp.async.commit_group;" ::: "memory");
    }

    float acc[4][8][4];
#pragma unroll
    for (int i = 0; i < 4; i++)
#pragma unroll
        for (int j = 0; j < 8; j++)
#pragma unroll
            for (int k = 0; k < 4; k++) acc[i][j][k] = 0.f;

    for (int it = 0; it < KT; it++) {
        asm volatile("cp.async.wait_group 2;" ::: "memory");
        __syncthreads();

        // issue next stage's loads BEFORE compute so they overlap the MMAs
        const int nk = it + STAGES - 1;
        if (nk < KT) load_stage(nk & (STAGES - 1), nk);
        asm volatile("cp.async.commit_group;" ::: "memory");

        const float* Asm = As + (it & (STAGES - 1)) * BM * PITCH;
        const float* Bsm = Bs + (it & (STAGES - 1)) * BN * PITCH;

#pragma unroll
        for (int kk = 0; kk < 4; kk++) {
            const int k0 = kk * 8 + (lane & 3);
            uint32_t af[4][4];
#pragma unroll
            for (int mi = 0; mi < 4; mi++) {
                const int rb = wm * 64 + mi * 16 + (lane >> 2);
                af[mi][0] = f2tf(Asm[rb * PITCH + k0]);
                af[mi][1] = f2tf(Asm[(rb + 8) * PITCH + k0]);
                af[mi][2] = f2tf(Asm[rb * PITCH + k0 + 4]);
                af[mi][3] = f2tf(Asm[(rb + 8) * PITCH + k0 + 4]);
            }
#pragma unroll
            for (int ni = 0; ni < 8; ni++) {
                const int cb = wn * 64 + ni * 8 + (lane >> 2);
                const uint32_t b0 = f2tf(Bsm[cb * PITCH + k0]);
                const uint32_t b1 = f2tf(Bsm[cb * PITCH + k0 + 4]);
#pragma unroll
                for (int mi = 0; mi < 4; mi++)
                    mma8(acc[mi][ni], af[mi], b0, b1);
            }
        }
    }

    // ---------- epilogue: write raw logits ----------
#pragma unroll
    for (int mi = 0; mi < 4; mi++) {
        const int row = m0 + wm * 64 + mi * 16 + (lane >> 2);
#pragma unroll
        for (int ni = 0; ni < 8; ni++) {
            const int col = n0 + wn * 64 + ni * 8 + (lane & 3) * 2;
            float2 v0 = make_float2(acc[mi][ni][0], acc[mi][ni][1]);
            float2 v1 = make_float2(acc[mi][ni][2], acc[mi][ni][3]);
            *reinterpret_cast<float2*>(&g_scratch[(size_t)row * NDIM + col])       = v0;
            *reinterpret_cast<float2*>(&g_scratch[(size_t)(row + 8) * NDIM + col]) = v1;
        }
    }
}

// ============================================================
// Pass 2: gate*sigmoid, softmax chunk combine, RMS-norm, RoPE
// ============================================================
__device__ __forceinline__ float sigmoidf_(float x) {
    return 1.0f / (1.0f + expf(-x));
}

__global__ void __launch_bounds__(512)
combine_kernel(const float* __restrict__ cosb,
               const float* __restrict__ sinb,
               const float* __restrict__ ape,
               const float* __restrict__ normw,
               float* __restrict__ out) {
    const int bc = blockIdx.x;
    const int b = bc >> 10;
    const int c = bc & (C_ - 1);
    const int d = threadIdx.x;

    float v[8];
#pragma unroll
    for (int r = 0; r < 4; r++) {
        v[r]     = ape[r * 1024 + d];
        v[4 + r] = ape[r * 1024 + 512 + d];
    }

    const size_t mb = (size_t)(b * S_ + c * RATIO);
    float acc = 0.f;

    if (c == 0) {
        float mx = fmaxf(fmaxf(v[0], v[1]), fmaxf(v[2], v[3]));
        float e[4], s = 0.f;
#pragma unroll
        for (int r = 0; r < 4; r++) { e[r] = expf(v[r] - mx); s += e[r]; }
        const float inv = 1.0f / s;
#pragma unroll
        for (int r = 0; r < 4; r++) {
            const size_t row = mb + r;
            const float kvv = g_scratch[row * NDIM + d];
            const float gv  = g_scratch[row * NDIM + 1024 + d];
            acc += kvv * sigmoidf_(gv) * (e[r] * inv);
        }
    } else {
        float mx = v[0];
#pragma unroll
        for (int r = 1; r < 8; r++) mx = fmaxf(mx, v[r]);
        float e[8], s = 0.f;
#pragma unroll
        for (int r = 0; r < 8; r++) { e[r] = expf(v[r] - mx); s += e[r]; }
        const float inv = 1.0f / s;
#pragma unroll
        for (int r = 0; r < 4; r++) {
            const size_t row = mb + r;
            const float kvv = g_scratch[row * NDIM + d];
            const float gv  = g_scratch[row * NDIM + 1024 + d];
            acc += kvv * sigmoidf_(gv) * (e[r] * inv);
        }
#pragma unroll
        for (int r = 0; r < 4; r++) {
            const size_t row = mb - RATIO + r;
            const float ovv = g_scratch[row * NDIM + 512 + d];
            const float gv  = g_scratch[row * NDIM + 1536 + d];
            acc += ovv * sigmoidf_(gv) * (e[4 + r] * inv);
        }
    }

    __shared__ float red[16];
    __shared__ float sv[512];
    __shared__ float s_scale;

    float sq = acc * acc;
#pragma unroll
    for (int o = 16; o > 0; o >>= 1) sq += __shfl_xor_sync(0xffffffffu, sq, o);
    const int wid = d >> 5, ln = d & 31;
    if (ln == 0) red[wid] = sq;
    __syncthreads();
    if (d == 0) {
        float t = 0.f;
#pragma unroll
        for (int i = 0; i < 16; i++) t += red[i];
        s_scale = rsqrtf(t * (1.0f / 512.0f) + 1e-6f);
    }
    __syncthreads();

    const float y = acc * s_scale * normw[d];
    sv[d] = y;
    __syncthreads();

    float res;
    if (d < HD - ROPE_D) {
        res = y;
    } else {
        const int j = d - (HD - ROPE_D);
        const int i = j >> 1;
        const float e = sv[(HD - ROPE_D) + 2 * i];
        const float o = sv[(HD - ROPE_D) + 2 * i + 1];
        const size_t ci = (size_t)(b * C_ + c) * (ROPE_D / 2) + i;
        const float cs = cosb[ci];
        const float sn = sinb[ci];
        res = ((j & 1) == 0) ? (e * cs - o * sn) : (e * sn + o * cs);
    }
    out[(size_t)(b * C_ + c) * HD + d] = res;
}

// ============================================================
// launch
// ============================================================
extern "C" void kernel_launch(void* const* d_in, const int* in_sizes, int n_in,
                              void* d_out, int out_size) {
    const float* x    = (const float*)d_in[0];
    const float* cosb = (const float*)d_in[1];
    const float* sinb = (const float*)d_in[2];
    const float* Wkv  = (const float*)d_in[3];
    const float* Wg   = (const float*)d_in[4];
    const float* ape  = (const float*)d_in[5];
    const float* nw   = (const float*)d_in[6];
    float* out = (float*)d_out;

    const size_t smem = (size_t)STAGES * (BM + BN) * PITCH * sizeof(float); // 221184
    cudaFuncSetAttribute(gemm_tf32_kernel,
                         cudaFuncAttributeMaxDynamicSharedMemorySize, (int)smem);

    gemm_tf32_kernel<<<(MDIM / BM) * (NDIM / BN), 256, smem>>>(x, Wkv, Wg);
    combine_kernel<<<B_ * C_, 512>>>(cosb, sinb, ape, nw, out);
}